// round 1
// baseline (speedup 1.0000x reference)
#include <cuda_runtime.h>
#include <cuda_bf16.h>

#define THREADS 256
#define ITERS   8
// elements per CTA = THREADS * 4 * ITERS = 8192 floats

__global__ __launch_bounds__(THREADS) void nf4_quant_kernel(
    const float* __restrict__ w,
    const float* __restrict__ log_scale,
    float* __restrict__ out,
    int n4)                      // total float4 count
{
    // Per-cell decision table: v in [-1,1] -> cell j = round(v*512 + 512), j in [0,1024].
    // Cell j covers v in [(j-0.5)/512 - 1, (j+0.5)/512 - 1). Each cell contains at most
    // one NF4 midpoint (cell width 0.00195 << min midpoint gap 0.085).
    // Entry: {m0 = midpoint in cell (or 2.0f if none), lvl_lo = NF4[b], lvl_hi = NF4[b+1]}
    // where b = #midpoints < cell_lo. Then idx-level = (v > m0) ? lvl_hi : lvl_lo. Exact.
    __shared__ float4 tbl[1025];

    {
        const float nf4[16] = {
            -1.0f, -0.6961928f, -0.52507305f, -0.39491749f, -0.28444138f,
            -0.18477343f, -0.09105004f, 0.0f, 0.0795803f, 0.1609302f,
            0.2461123f, 0.33791524f, 0.44070983f, 0.562617f, 0.72295684f, 1.0f};
        for (int t = threadIdx.x; t < 1025; t += THREADS) {
            float lo = ((float)t - 0.5f) * (1.0f / 512.0f) - 1.0f;
            float hi = ((float)t + 0.5f) * (1.0f / 512.0f) - 1.0f;
            int   b  = 0;
            float m0 = 2.0f;   // sentinel: nothing exceeds it (v <= 1)
            #pragma unroll
            for (int i = 0; i < 15; i++) {
                float mid = 0.5f * (nf4[i] + nf4[i + 1]);
                if (mid < lo)        b++;
                else if (mid < hi)   m0 = mid;   // at most one per cell
            }
            float lvl_lo = nf4[b];
            float lvl_hi = nf4[b + 1 < 16 ? b + 1 : 15];
            tbl[t] = make_float4(m0, lvl_lo, lvl_hi, 0.0f);
        }
    }
    __syncthreads();

    const float e = expf(__ldg(log_scale));

    const float4* __restrict__ w4 = (const float4*)w;
    float4* __restrict__       o4 = (float4*)out;

    const int base = blockIdx.x * (THREADS * ITERS) + threadIdx.x;

    // software-pipelined: prefetch next tile's float4 before computing current
    float4 cur = make_float4(0.f, 0.f, 0.f, 0.f);
    if (base < n4) cur = w4[base];

    #pragma unroll
    for (int i = 0; i < ITERS; i++) {
        const int idx = base + i * THREADS;
        float4 nxt = make_float4(0.f, 0.f, 0.f, 0.f);
        if (i + 1 < ITERS) {
            int nidx = idx + THREADS;
            if (nidx < n4) nxt = w4[nidx];
        }

        // block absmax over 64 consecutive floats = 16 consecutive lanes x float4
        float m = fmaxf(fmaxf(fabsf(cur.x), fabsf(cur.y)),
                        fmaxf(fabsf(cur.z), fabsf(cur.w)));
        m = fmaxf(m, __shfl_xor_sync(0xffffffffu, m, 1));
        m = fmaxf(m, __shfl_xor_sync(0xffffffffu, m, 2));
        m = fmaxf(m, __shfl_xor_sync(0xffffffffu, m, 4));
        m = fmaxf(m, __shfl_xor_sync(0xffffffffu, m, 8));

        const float scale = fmaxf(m * e, 1e-6f);
        const float inv   = 1.0f / scale;

        float4 r;
        {
            float vx = fminf(fmaxf(cur.x * inv, -1.0f), 1.0f);
            float vy = fminf(fmaxf(cur.y * inv, -1.0f), 1.0f);
            float vz = fminf(fmaxf(cur.z * inv, -1.0f), 1.0f);
            float vw = fminf(fmaxf(cur.w * inv, -1.0f), 1.0f);

            // j = round(v*512 + 512) via float-bit trick: single FMA into 2^23 window
            int jx = __float_as_int(fmaf(vx, 512.0f, 512.0f + 8388608.0f)) & 0x3FFFFF;
            int jy = __float_as_int(fmaf(vy, 512.0f, 512.0f + 8388608.0f)) & 0x3FFFFF;
            int jz = __float_as_int(fmaf(vz, 512.0f, 512.0f + 8388608.0f)) & 0x3FFFFF;
            int jw = __float_as_int(fmaf(vw, 512.0f, 512.0f + 8388608.0f)) & 0x3FFFFF;

            float4 ex = tbl[jx];
            float4 ey = tbl[jy];
            float4 ez = tbl[jz];
            float4 ew = tbl[jw];

            r.x = ((vx > ex.x) ? ex.z : ex.y) * scale;
            r.y = ((vy > ey.x) ? ey.z : ey.y) * scale;
            r.z = ((vz > ez.x) ? ez.z : ez.y) * scale;
            r.w = ((vw > ew.x) ? ew.z : ew.y) * scale;
        }

        if (idx < n4) o4[idx] = r;
        cur = nxt;
    }
}

extern "C" void kernel_launch(void* const* d_in, const int* in_sizes, int n_in,
                              void* d_out, int out_size)
{
    const float* w  = (const float*)d_in[0];
    const float* ls = (const float*)d_in[1];
    float* out      = (float*)d_out;

    const int n  = in_sizes[0];          // 8192*8192, divisible by 64
    const int n4 = n >> 2;               // float4 count
    const int elemsPerCta = THREADS * ITERS;          // float4 per CTA
    const int grid = (n4 + elemsPerCta - 1) / elemsPerCta;

    nf4_quant_kernel<<<grid, THREADS>>>(w, ls, out, n4);
}